// round 3
// baseline (speedup 1.0000x reference)
#include <cuda_runtime.h>
#include <cuda_bf16.h>
#include <math.h>

// Problem constants
#define BB 2
#define TT 1024
#define CC 512
#define HH 8
#define DD 64
#define LL 4
#define VV 32000

// Scratch buffers (no cudaMalloc allowed)
__device__ float g_x [BB*TT*CC];      // residual stream
__device__ float g_h [BB*TT*CC];      // LN output
__device__ float g_q [BB*TT*CC];
__device__ float g_k [BB*TT*CC];
__device__ float g_v [BB*TT*CC];
__device__ float g_y [BB*TT*CC];      // attention output
__device__ float g_h1[BB*TT*4*CC];    // MLP hidden

// ---------------------------------------------------------------------------
// Embedding: x[b,t,c] = tok_emb[idx[b,t],c] + pos_emb[t,c]
// ---------------------------------------------------------------------------
__global__ void embed_kernel(const int* __restrict__ idx,
                             const float* __restrict__ tok,
                             const float* __restrict__ pos,
                             float* __restrict__ x)
{
    int i  = blockIdx.x * blockDim.x + threadIdx.x;   // over BB*TT*(CC/4)
    int c4 = (i & 127) << 2;
    int bt = i >> 7;
    int t  = bt & (TT - 1);
    int row = idx[bt];
    float4 a = *(const float4*)&tok[row * CC + c4];
    float4 p = *(const float4*)&pos[t   * CC + c4];
    float4 o;
    o.x = a.x + p.x; o.y = a.y + p.y; o.z = a.z + p.z; o.w = a.w + p.w;
    *(float4*)&x[bt * CC + c4] = o;
}

// ---------------------------------------------------------------------------
// LayerNorm: one block (128 thr) per row of 512
// ---------------------------------------------------------------------------
__global__ __launch_bounds__(128) void ln_kernel(const float* __restrict__ x,
                                                 const float* __restrict__ w,
                                                 const float* __restrict__ b,
                                                 float* __restrict__ out)
{
    __shared__ float red[4];
    const int row = blockIdx.x;
    const int tid = threadIdx.x;

    float4 v = *(const float4*)&x[row * CC + tid * 4];
    float s = v.x + v.y + v.z + v.w;
    #pragma unroll
    for (int o = 16; o; o >>= 1) s += __shfl_xor_sync(0xffffffffu, s, o);
    if ((tid & 31) == 0) red[tid >> 5] = s;
    __syncthreads();
    float mean = (red[0] + red[1] + red[2] + red[3]) * (1.0f / CC);

    float d0 = v.x - mean, d1 = v.y - mean, d2 = v.z - mean, d3 = v.w - mean;
    float ss = d0*d0 + d1*d1 + d2*d2 + d3*d3;
    #pragma unroll
    for (int o = 16; o; o >>= 1) ss += __shfl_xor_sync(0xffffffffu, ss, o);
    __syncthreads();
    if ((tid & 31) == 0) red[tid >> 5] = ss;
    __syncthreads();
    float var  = (red[0] + red[1] + red[2] + red[3]) * (1.0f / CC);
    float rstd = rsqrtf(var + 1e-5f);

    float4 wv = *(const float4*)&w[tid * 4];
    float4 bv = *(const float4*)&b[tid * 4];
    float4 o4;
    o4.x = d0 * rstd * wv.x + bv.x;
    o4.y = d1 * rstd * wv.y + bv.y;
    o4.z = d2 * rstd * wv.z + bv.z;
    o4.w = d3 * rstd * wv.w + bv.w;
    *(float4*)&out[row * CC + tid * 4] = o4;
}

// ---------------------------------------------------------------------------
// GEMM: C[M,N] = A[M,K] @ B[K,N] (+bias) (+resid) (gelu)
// Tile BM x 128, BK=8, BM*2 threads, 8x8 micro-tile, double-buffered smem.
// BM=128 (256 thr) for big-N shapes; BM=64 (128 thr) for N=512 shapes so the
// grid reaches >=128 blocks (wave coverage on 148 SMs).
// MODE: 0 = (+bias), 1 = (+bias +resid), 2 = gelu(+bias)
// Assumes M%BM==0, N%128==0, K%8==0 (true for all shapes here).
// ---------------------------------------------------------------------------
template<int MODE, int BM>
__global__ __launch_bounds__(256) void gemm_kernel(
    const float* __restrict__ A, const float* __restrict__ B,
    const float* __restrict__ bias, const float* __restrict__ resid,
    float* __restrict__ C, int M, int N, int K)
{
    const int BK = 8;
    const int NT = BM * 2;          // threads
    const int PER_B = 128 / BM;     // B-tile float4 loads per thread (1 or 2)
    __shared__ float As[2][BK][BM];   // A transposed into [k][m]
    __shared__ float Bs[2][BK][128];

    const int tid = threadIdx.x;
    const int tx  = tid & 15;       // 16 col groups
    const int ty  = tid >> 4;       // BM/8 row groups
    const int bm  = blockIdx.y * BM;
    const int bn  = blockIdx.x * 128;

    // A tile load mapping: BM rows x 8 cols = BM*2 float4 -> 1 per thread
    const int ar = tid >> 1;
    const int ak = (tid & 1) << 2;
    // B tile load mapping: 8 rows x 128 cols = 256 float4 -> PER_B per thread
    int br_[PER_B], bc_[PER_B];
    #pragma unroll
    for (int j = 0; j < PER_B; j++) {
        int idx = tid + j * NT;
        br_[j] = idx >> 5;
        bc_[j] = (idx & 31) << 2;
    }

    const float* Aptr = A + (bm + ar) * K + ak;

    float acc[8][8];
    #pragma unroll
    for (int i = 0; i < 8; i++)
        #pragma unroll
        for (int j = 0; j < 8; j++) acc[i][j] = 0.0f;

    // preload tile 0
    {
        float4 pa = *(const float4*)(Aptr);
        As[0][ak + 0][ar] = pa.x;
        As[0][ak + 1][ar] = pa.y;
        As[0][ak + 2][ar] = pa.z;
        As[0][ak + 3][ar] = pa.w;
        #pragma unroll
        for (int j = 0; j < PER_B; j++)
            *(float4*)&Bs[0][br_[j]][bc_[j]] =
                *(const float4*)(B + br_[j] * N + bn + bc_[j]);
    }
    __syncthreads();

    const int nk = K / BK;
    int buf = 0;
    for (int kt = 0; kt < nk; kt++) {
        float4 pa, pb[PER_B];
        const bool has_next = (kt + 1 < nk);
        if (has_next) {
            pa = *(const float4*)(Aptr + (kt + 1) * BK);
            #pragma unroll
            for (int j = 0; j < PER_B; j++)
                pb[j] = *(const float4*)(B + ((kt + 1) * BK + br_[j]) * N + bn + bc_[j]);
        }

        #pragma unroll
        for (int kk = 0; kk < BK; kk++) {
            float4 a0 = *(const float4*)&As[buf][kk][ty * 4];
            float4 a1 = *(const float4*)&As[buf][kk][ty * 4 + BM / 2];
            float4 b0 = *(const float4*)&Bs[buf][kk][tx * 4];
            float4 b1 = *(const float4*)&Bs[buf][kk][tx * 4 + 64];
            float af[8] = {a0.x, a0.y, a0.z, a0.w, a1.x, a1.y, a1.z, a1.w};
            float bf[8] = {b0.x, b0.y, b0.z, b0.w, b1.x, b1.y, b1.z, b1.w};
            #pragma unroll
            for (int i = 0; i < 8; i++)
                #pragma unroll
                for (int j = 0; j < 8; j++)
                    acc[i][j] += af[i] * bf[j];
        }

        if (has_next) {
            int nb = buf ^ 1;
            As[nb][ak + 0][ar] = pa.x;
            As[nb][ak + 1][ar] = pa.y;
            As[nb][ak + 2][ar] = pa.z;
            As[nb][ak + 3][ar] = pa.w;
            #pragma unroll
            for (int j = 0; j < PER_B; j++)
                *(float4*)&Bs[nb][br_[j]][bc_[j]] = pb[j];
            __syncthreads();
            buf = nb;
        }
    }

    // epilogue: rows = ty*4+i (i<4) and BM/2+ty*4+(i-4); cols = tx*4, 64+tx*4
    float bv0[4] = {0.f, 0.f, 0.f, 0.f};
    float bv1[4] = {0.f, 0.f, 0.f, 0.f};
    const int col0 = bn + tx * 4;
    const int col1 = bn + tx * 4 + 64;
    if (bias) {
        float4 t0 = *(const float4*)(bias + col0);
        float4 t1 = *(const float4*)(bias + col1);
        bv0[0] = t0.x; bv0[1] = t0.y; bv0[2] = t0.z; bv0[3] = t0.w;
        bv1[0] = t1.x; bv1[1] = t1.y; bv1[2] = t1.z; bv1[3] = t1.w;
    }
    #pragma unroll
    for (int i = 0; i < 8; i++) {
        const int row = bm + ((i < 4) ? (ty * 4 + i) : (BM / 2 + ty * 4 + i - 4));
        float o[8];
        #pragma unroll
        for (int j = 0; j < 4; j++) { o[j] = acc[i][j] + bv0[j]; o[4 + j] = acc[i][4 + j] + bv1[j]; }
        if (MODE == 1) {
            float4 r0 = *(const float4*)(resid + row * N + col0);
            float4 r1 = *(const float4*)(resid + row * N + col1);
            o[0] += r0.x; o[1] += r0.y; o[2] += r0.z; o[3] += r0.w;
            o[4] += r1.x; o[5] += r1.y; o[6] += r1.z; o[7] += r1.w;
        }
        if (MODE == 2) {
            #pragma unroll
            for (int j = 0; j < 8; j++)
                o[j] = 0.5f * o[j] * (1.0f + erff(o[j] * 0.70710678118654752f));
        }
        float4 s0 = {o[0], o[1], o[2], o[3]};
        float4 s1 = {o[4], o[5], o[6], o[7]};
        *(float4*)(C + row * N + col0) = s0;
        *(float4*)(C + row * N + col1) = s1;
    }
}

// ---------------------------------------------------------------------------
// Flash attention (fp32, causal). Block = 128 threads, handles 16 query rows
// of one (b,h). Key/value tiles of 64. Online softmax.
// Q,K,V,Y layout: [B,T,C] with head h at columns h*64..h*64+63.
// ---------------------------------------------------------------------------
__global__ __launch_bounds__(128) void attn_kernel(
    const float* __restrict__ Q, const float* __restrict__ K,
    const float* __restrict__ V, float* __restrict__ Y)
{
    const int qt = blockIdx.x;   // query tile (16 rows)
    const int h  = blockIdx.y;
    const int b  = blockIdx.z;

    __shared__ float Qs[16][68];
    __shared__ float Ks[64][68];
    __shared__ float Vs[64][68];
    __shared__ float Ps[16][65];
    __shared__ float m_s[16], l_s[16];

    const int tid = threadIdx.x;
    const int r  = tid >> 3;   // query row in tile (0..15)
    const int sb = tid & 7;    // sub-lane (key / d sub-index)

    // load Q tile (16 x 64)
    for (int i = tid; i < 16 * 16; i += 128) {
        int rr = i >> 4, c4 = (i & 15) << 2;
        *(float4*)&Qs[rr][c4] =
            *(const float4*)&Q[((b * TT + qt * 16 + rr) * CC) + h * DD + c4];
    }
    if (tid < 16) { m_s[tid] = -1e30f; l_s[tid] = 0.0f; }

    float acc[8];
    #pragma unroll
    for (int j = 0; j < 8; j++) acc[j] = 0.0f;

    const int qg  = qt * 16 + r;
    const int nkt = ((qt * 16 + 15) >> 6) + 1;

    for (int kt = 0; kt < nkt; kt++) {
        __syncthreads();
        // load K,V tiles (64 x 64 each)
        for (int i = tid; i < 64 * 16; i += 128) {
            int rr = i >> 4, c4 = (i & 15) << 2;
            int g  = ((b * TT + kt * 64 + rr) * CC) + h * DD + c4;
            *(float4*)&Ks[rr][c4] = *(const float4*)&K[g];
            *(float4*)&Vs[rr][c4] = *(const float4*)&V[g];
        }
        __syncthreads();

        // scores for 8 keys per thread
        float sv[8];
        #pragma unroll
        for (int j = 0; j < 8; j++) sv[j] = 0.0f;
        for (int d = 0; d < 64; d++) {
            float qv = Qs[r][d];
            #pragma unroll
            for (int j = 0; j < 8; j++) sv[j] += qv * Ks[sb + 8 * j][d];
        }
        float tmax = -1e30f;
        #pragma unroll
        for (int j = 0; j < 8; j++) {
            int sg = kt * 64 + sb + 8 * j;
            sv[j] = (sg <= qg) ? sv[j] * 0.125f : -1e30f;
            tmax = fmaxf(tmax, sv[j]);
        }
        #pragma unroll
        for (int o = 4; o; o >>= 1)
            tmax = fmaxf(tmax, __shfl_xor_sync(0xffffffffu, tmax, o, 8));

        float m_old = m_s[r];
        float m_new = fmaxf(m_old, tmax);
        float psum = 0.0f;
        #pragma unroll
        for (int j = 0; j < 8; j++) {
            float p = expf(sv[j] - m_new);
            Ps[r][sb + 8 * j] = p;
            psum += p;
        }
        #pragma unroll
        for (int o = 4; o; o >>= 1)
            psum += __shfl_xor_sync(0xffffffffu, psum, o, 8);

        float alpha = expf(m_old - m_new);
        if (sb == 0) { m_s[r] = m_new; l_s[r] = l_s[r] * alpha + psum; }
        __syncwarp();

        #pragma unroll
        for (int j = 0; j < 8; j++) acc[j] *= alpha;
        for (int s = 0; s < 64; s++) {
            float p = Ps[r][s];
            #pragma unroll
            for (int j = 0; j < 8; j++) acc[j] += p * Vs[s][sb + 8 * j];
        }
        __syncwarp();
    }

    float inv_l = 1.0f / l_s[r];
    #pragma unroll
    for (int j = 0; j < 8; j++)
        Y[((b * TT + qg) * CC) + h * DD + sb + 8 * j] = acc[j] * inv_l;
}

// ---------------------------------------------------------------------------
// Launch
// ---------------------------------------------------------------------------
extern "C" void kernel_launch(void* const* d_in, const int* in_sizes, int n_in,
                              void* d_out, int out_size)
{
    const int*   idx   = (const int*)  d_in[0];
    const float* tok   = (const float*)d_in[1];
    const float* pos   = (const float*)d_in[2];
    const float* ln1w  = (const float*)d_in[3];
    const float* ln1b  = (const float*)d_in[4];
    const float* Wq    = (const float*)d_in[5];
    const float* bq    = (const float*)d_in[6];
    const float* Wk    = (const float*)d_in[7];
    const float* bk    = (const float*)d_in[8];
    const float* Wv    = (const float*)d_in[9];
    const float* bv    = (const float*)d_in[10];
    const float* Wo    = (const float*)d_in[11];
    const float* bo    = (const float*)d_in[12];
    const float* ln2w  = (const float*)d_in[13];
    const float* ln2b  = (const float*)d_in[14];
    const float* W1    = (const float*)d_in[15];
    const float* b1    = (const float*)d_in[16];
    const float* W2    = (const float*)d_in[17];
    const float* b2    = (const float*)d_in[18];
    const float* lnfw  = (const float*)d_in[19];
    const float* lnfb  = (const float*)d_in[20];
    const float* Whead = (const float*)d_in[21];
    float* out = (float*)d_out;

    float *x, *h, *q, *k, *v, *y, *h1;
    cudaGetSymbolAddress((void**)&x,  g_x);
    cudaGetSymbolAddress((void**)&h,  g_h);
    cudaGetSymbolAddress((void**)&q,  g_q);
    cudaGetSymbolAddress((void**)&k,  g_k);
    cudaGetSymbolAddress((void**)&v,  g_v);
    cudaGetSymbolAddress((void**)&y,  g_y);
    cudaGetSymbolAddress((void**)&h1, g_h1);

    const int M = BB * TT;                   // 2048
    embed_kernel<<<(M * CC / 4 + 255) / 256, 256>>>(idx, tok, pos, x);

    for (int i = 0; i < LL; i++) {
        const int wOff  = i * CC * CC;       // 262144
        const int bOff  = i * CC;
        const int w1Off = i * CC * 4 * CC;   // 1048576
        const int b1Off = i * 4 * CC;

        ln_kernel<<<M, 128>>>(x, ln1w + bOff, ln1b + bOff, h);

        // N=512 shapes: BM=64 tiles -> 128 blocks (wave coverage)
        gemm_kernel<0, 64><<<dim3(CC / 128, M / 64), 128>>>(h, Wq + wOff, bq + bOff, nullptr, q, M, CC, CC);
        gemm_kernel<0, 64><<<dim3(CC / 128, M / 64), 128>>>(h, Wk + wOff, bk + bOff, nullptr, k, M, CC, CC);
        gemm_kernel<0, 64><<<dim3(CC / 128, M / 64), 128>>>(h, Wv + wOff, bv + bOff, nullptr, v, M, CC, CC);

        attn_kernel<<<dim3(TT / 16, HH, BB), 128>>>(q, k, v, y);

        gemm_kernel<1, 64><<<dim3(CC / 128, M / 64), 128>>>(y, Wo + wOff, bo + bOff, x, x, M, CC, CC);

        ln_kernel<<<M, 128>>>(x, ln2w + bOff, ln2b + bOff, h);

        gemm_kernel<2, 128><<<dim3(4 * CC / 128, M / 128), 256>>>(h, W1 + w1Off, b1 + b1Off, nullptr, h1, M, 4 * CC, CC);
        gemm_kernel<1, 64><<<dim3(CC / 128, M / 64), 128>>>(h1, W2 + w1Off, b2 + bOff, x, x, M, CC, 4 * CC);
    }

    ln_kernel<<<M, 128>>>(x, lnfw, lnfb, h);
    gemm_kernel<0, 128><<<dim3(VV / 128, M / 128), 256>>>(h, Whead, nullptr, nullptr, out, M, VV, CC);
}

// round 4
// speedup vs baseline: 1.7502x; 1.7502x over previous
#include <cuda_runtime.h>
#include <cuda_bf16.h>
#include <math.h>
#include <stdint.h>

// Problem constants
#define BB 2
#define TT 1024
#define CC 512
#define HH 8
#define DD 64
#define LL 4
#define VV 32000

// Scratch buffers (no cudaMalloc allowed)
__device__ float g_x [BB*TT*CC];      // residual stream
__device__ float g_h [BB*TT*CC];      // LN output
__device__ float g_q [BB*TT*CC];
__device__ float g_k [BB*TT*CC];
__device__ float g_v [BB*TT*CC];
__device__ float g_y [BB*TT*CC];      // attention output
__device__ float g_h1[BB*TT*4*CC];    // MLP hidden

// ---------------------------------------------------------------------------
// Embedding
// ---------------------------------------------------------------------------
__global__ void embed_kernel(const int* __restrict__ idx,
                             const float* __restrict__ tok,
                             const float* __restrict__ pos,
                             float* __restrict__ x)
{
    int i  = blockIdx.x * blockDim.x + threadIdx.x;
    int c4 = (i & 127) << 2;
    int bt = i >> 7;
    int t  = bt & (TT - 1);
    int row = idx[bt];
    float4 a = *(const float4*)&tok[row * CC + c4];
    float4 p = *(const float4*)&pos[t   * CC + c4];
    float4 o;
    o.x = a.x + p.x; o.y = a.y + p.y; o.z = a.z + p.z; o.w = a.w + p.w;
    *(float4*)&x[bt * CC + c4] = o;
}

// ---------------------------------------------------------------------------
// LayerNorm: one block (128 thr) per row of 512
// ---------------------------------------------------------------------------
__global__ __launch_bounds__(128) void ln_kernel(const float* __restrict__ x,
                                                 const float* __restrict__ w,
                                                 const float* __restrict__ b,
                                                 float* __restrict__ out)
{
    __shared__ float red[4];
    const int row = blockIdx.x;
    const int tid = threadIdx.x;

    float4 v = *(const float4*)&x[row * CC + tid * 4];
    float s = v.x + v.y + v.z + v.w;
    #pragma unroll
    for (int o = 16; o; o >>= 1) s += __shfl_xor_sync(0xffffffffu, s, o);
    if ((tid & 31) == 0) red[tid >> 5] = s;
    __syncthreads();
    float mean = (red[0] + red[1] + red[2] + red[3]) * (1.0f / CC);

    float d0 = v.x - mean, d1 = v.y - mean, d2 = v.z - mean, d3 = v.w - mean;
    float ss = d0*d0 + d1*d1 + d2*d2 + d3*d3;
    #pragma unroll
    for (int o = 16; o; o >>= 1) ss += __shfl_xor_sync(0xffffffffu, ss, o);
    __syncthreads();
    if ((tid & 31) == 0) red[tid >> 5] = ss;
    __syncthreads();
    float var  = (red[0] + red[1] + red[2] + red[3]) * (1.0f / CC);
    float rstd = rsqrtf(var + 1e-5f);

    float4 wv = *(const float4*)&w[tid * 4];
    float4 bv = *(const float4*)&b[tid * 4];
    float4 o4;
    o4.x = d0 * rstd * wv.x + bv.x;
    o4.y = d1 * rstd * wv.y + bv.y;
    o4.z = d2 * rstd * wv.z + bv.z;
    o4.w = d3 * rstd * wv.w + bv.w;
    *(float4*)&out[row * CC + tid * 4] = o4;
}

// ---------------------------------------------------------------------------
// Tensor-core GEMM with bf16x3 split (hi*hi + hi*lo + lo*hi), fp32 accum.
// C[M,N] = A[M,K] @ B[K,N] (+bias)(+resid)(gelu).  rel err ~1.5e-5.
// Tile: BM=128, BN=64, BK=32. 256 threads = 8 warps (4 along M x 2 along N),
// warp tile 32x32 = 2 m16-tiles x 4 n8-tiles. Double-buffered smem,
// XOR-swizzled for conflict-free fragment loads. 48KB smem exactly.
// Requires M%128==0, N%64==0, K%32==0 (true for all shapes here).
// ---------------------------------------------------------------------------
#define SWZ(r) ((((r) >> 1) & 3) << 2)

__device__ __forceinline__ void mma_bf16(float* c, const uint32_t* a, const uint32_t* b)
{
    asm volatile(
        "mma.sync.aligned.m16n8k16.row.col.f32.bf16.bf16.f32 "
        "{%0,%1,%2,%3}, {%4,%5,%6,%7}, {%8,%9}, {%0,%1,%2,%3};"
        : "+f"(c[0]), "+f"(c[1]), "+f"(c[2]), "+f"(c[3])
        : "r"(a[0]), "r"(a[1]), "r"(a[2]), "r"(a[3]), "r"(b[0]), "r"(b[1]));
}

__device__ __forceinline__ uint32_t pack_bf16(float x, float y)
{
    __nv_bfloat162 t;
    t.x = __float2bfloat16(x);
    t.y = __float2bfloat16(y);
    return *(uint32_t*)&t;
}

template<int MODE>
__global__ __launch_bounds__(256) void gemm_tc(
    const float* __restrict__ A, const float* __restrict__ B,
    const float* __restrict__ bias, const float* __restrict__ resid,
    float* __restrict__ C, int M, int N, int K)
{
    __shared__ uint32_t As[2][2][128][16];   // [stage][hi/lo][m][kword]
    __shared__ uint32_t Bs[2][2][64][16];    // [stage][hi/lo][n][kword]

    const int tid = threadIdx.x;
    const int lid = tid & 31;
    const int wid = tid >> 5;
    const int warp_m = wid & 3;          // 4 warps along M (32 rows each)
    const int warp_n = wid >> 2;         // 2 warps along N (32 cols each)
    const int bm = blockIdx.y * 128;
    const int bn = blockIdx.x * 64;

    // global load mappings
    const int a_r  = tid >> 3;           // 0..31 (plus it*32)
    const int a_c  = (tid & 7) << 2;     // float4 col in k
    const int b_kp = tid >> 4;           // k-pair 0..15
    const int b_nq = (tid & 15) << 2;    // n offset (4 cols)

    float acc[2][4][4];
    #pragma unroll
    for (int i = 0; i < 2; i++)
        #pragma unroll
        for (int j = 0; j < 4; j++)
            #pragma unroll
            for (int q = 0; q < 4; q++) acc[i][j][q] = 0.0f;

    float4 pa[4], pb0, pb1;

    // ---- load stage 0 to regs
    #pragma unroll
    for (int it = 0; it < 4; it++)
        pa[it] = *(const float4*)(A + (size_t)(bm + a_r + it * 32) * K + a_c);
    pb0 = *(const float4*)(B + (size_t)(2 * b_kp)     * N + bn + b_nq);
    pb1 = *(const float4*)(B + (size_t)(2 * b_kp + 1) * N + bn + b_nq);

    const int nst = K / 32;
    int buf = 0;

    // ---- convert + store stage 0
    {
        #pragma unroll
        for (int it = 0; it < 4; it++) {
            int m = a_r + it * 32;
            int w0 = (tid & 7) << 1;
            int ph = w0 ^ SWZ(m);
            float4 f = pa[it];
            float hx = __bfloat162float(__float2bfloat16(f.x));
            float hy = __bfloat162float(__float2bfloat16(f.y));
            float hz = __bfloat162float(__float2bfloat16(f.z));
            float hw = __bfloat162float(__float2bfloat16(f.w));
            *(uint2*)&As[0][0][m][ph] = make_uint2(pack_bf16(hx, hy), pack_bf16(hz, hw));
            *(uint2*)&As[0][1][m][ph] = make_uint2(pack_bf16(f.x - hx, f.y - hy),
                                                   pack_bf16(f.z - hz, f.w - hw));
        }
        float f0[4] = {pb0.x, pb0.y, pb0.z, pb0.w};
        float f1[4] = {pb1.x, pb1.y, pb1.z, pb1.w};
        #pragma unroll
        for (int j = 0; j < 4; j++) {
            int n = b_nq + j;
            int ph = b_kp ^ SWZ(n);
            float h0 = __bfloat162float(__float2bfloat16(f0[j]));
            float h1 = __bfloat162float(__float2bfloat16(f1[j]));
            Bs[0][0][n][ph] = pack_bf16(h0, h1);
            Bs[0][1][n][ph] = pack_bf16(f0[j] - h0, f1[j] - h1);
        }
    }
    __syncthreads();

    for (int st = 0; st < nst; st++) {
        const bool has_next = (st + 1 < nst);
        if (has_next) {
            int k0 = (st + 1) * 32;
            #pragma unroll
            for (int it = 0; it < 4; it++)
                pa[it] = *(const float4*)(A + (size_t)(bm + a_r + it * 32) * K + k0 + a_c);
            pb0 = *(const float4*)(B + (size_t)(k0 + 2 * b_kp)     * N + bn + b_nq);
            pb1 = *(const float4*)(B + (size_t)(k0 + 2 * b_kp + 1) * N + bn + b_nq);
        }

        // ---- compute two k16 chunks of this stage
        #pragma unroll
        for (int s = 0; s <= 8; s += 8) {
            const int c = lid & 3;
            uint32_t Af[2][2][4];   // [hl][mt][4]
            uint32_t Bf[2][4][2];   // [hl][nt][2]
            #pragma unroll
            for (int mt = 0; mt < 2; mt++) {
                int m0 = warp_m * 32 + mt * 16 + (lid >> 2);
                int m1 = m0 + 8;
                int p0 = (s + c)     ^ SWZ(m0);
                int p1 = (s + c)     ^ SWZ(m1);
                int p2 = (s + 4 + c) ^ SWZ(m0);
                int p3 = (s + 4 + c) ^ SWZ(m1);
                #pragma unroll
                for (int hl = 0; hl < 2; hl++) {
                    Af[hl][mt][0] = As[buf][hl][m0][p0];
                    Af[hl][mt][1] = As[buf][hl][m1][p1];
                    Af[hl][mt][2] = As[buf][hl][m0][p2];
                    Af[hl][mt][3] = As[buf][hl][m1][p3];
                }
            }
            #pragma unroll
            for (int nt = 0; nt < 4; nt++) {
                int n0 = warp_n * 32 + nt * 8 + (lid >> 2);
                int p0 = (s + c)     ^ SWZ(n0);
                int p1 = (s + 4 + c) ^ SWZ(n0);
                #pragma unroll
                for (int hl = 0; hl < 2; hl++) {
                    Bf[hl][nt][0] = Bs[buf][hl][n0][p0];
                    Bf[hl][nt][1] = Bs[buf][hl][n0][p1];
                }
            }
            #pragma unroll
            for (int mt = 0; mt < 2; mt++)
                #pragma unroll
                for (int nt = 0; nt < 4; nt++) {
                    mma_bf16(acc[mt][nt], Af[0][mt], Bf[0][nt]);   // hi*hi
                    mma_bf16(acc[mt][nt], Af[0][mt], Bf[1][nt]);   // hi*lo
                    mma_bf16(acc[mt][nt], Af[1][mt], Bf[0][nt]);   // lo*hi
                }
        }

        if (has_next) {
            int nb = buf ^ 1;
            #pragma unroll
            for (int it = 0; it < 4; it++) {
                int m = a_r + it * 32;
                int w0 = (tid & 7) << 1;
                int ph = w0 ^ SWZ(m);
                float4 f = pa[it];
                float hx = __bfloat162float(__float2bfloat16(f.x));
                float hy = __bfloat162float(__float2bfloat16(f.y));
                float hz = __bfloat162float(__float2bfloat16(f.z));
                float hw = __bfloat162float(__float2bfloat16(f.w));
                *(uint2*)&As[nb][0][m][ph] = make_uint2(pack_bf16(hx, hy), pack_bf16(hz, hw));
                *(uint2*)&As[nb][1][m][ph] = make_uint2(pack_bf16(f.x - hx, f.y - hy),
                                                        pack_bf16(f.z - hz, f.w - hw));
            }
            float f0[4] = {pb0.x, pb0.y, pb0.z, pb0.w};
            float f1[4] = {pb1.x, pb1.y, pb1.z, pb1.w};
            #pragma unroll
            for (int j = 0; j < 4; j++) {
                int n = b_nq + j;
                int ph = b_kp ^ SWZ(n);
                float h0 = __bfloat162float(__float2bfloat16(f0[j]));
                float h1 = __bfloat162float(__float2bfloat16(f1[j]));
                Bs[nb][0][n][ph] = pack_bf16(h0, h1);
                Bs[nb][1][n][ph] = pack_bf16(f0[j] - h0, f1[j] - h1);
            }
            __syncthreads();
            buf = nb;
        }
    }

    // ---- epilogue
    #pragma unroll
    for (int mt = 0; mt < 2; mt++) {
        #pragma unroll
        for (int nt = 0; nt < 4; nt++) {
            int r0 = bm + warp_m * 32 + mt * 16 + (lid >> 2);
            int cc = bn + warp_n * 32 + nt * 8 + ((lid & 3) << 1);
            float2 bb = make_float2(0.0f, 0.0f);
            if (bias) bb = *(const float2*)(bias + cc);
            float* a4 = acc[mt][nt];
            #pragma unroll
            for (int half = 0; half < 2; half++) {
                int row = r0 + half * 8;
                float o0 = a4[half * 2 + 0] + bb.x;
                float o1 = a4[half * 2 + 1] + bb.y;
                if (MODE == 1) {
                    float2 rr = *(const float2*)(resid + (size_t)row * N + cc);
                    o0 += rr.x; o1 += rr.y;
                }
                if (MODE == 2) {
                    o0 = 0.5f * o0 * (1.0f + erff(o0 * 0.70710678118654752f));
                    o1 = 0.5f * o1 * (1.0f + erff(o1 * 0.70710678118654752f));
                }
                *(float2*)(C + (size_t)row * N + cc) = make_float2(o0, o1);
            }
        }
    }
}

// ---------------------------------------------------------------------------
// Flash attention (fp32, causal). Unchanged from round 3 baseline.
// ---------------------------------------------------------------------------
__global__ __launch_bounds__(128) void attn_kernel(
    const float* __restrict__ Q, const float* __restrict__ K,
    const float* __restrict__ V, float* __restrict__ Y)
{
    const int qt = blockIdx.x;
    const int h  = blockIdx.y;
    const int b  = blockIdx.z;

    __shared__ float Qs[16][68];
    __shared__ float Ks[64][68];
    __shared__ float Vs[64][68];
    __shared__ float Ps[16][65];
    __shared__ float m_s[16], l_s[16];

    const int tid = threadIdx.x;
    const int r  = tid >> 3;
    const int sb = tid & 7;

    for (int i = tid; i < 16 * 16; i += 128) {
        int rr = i >> 4, c4 = (i & 15) << 2;
        *(float4*)&Qs[rr][c4] =
            *(const float4*)&Q[((b * TT + qt * 16 + rr) * CC) + h * DD + c4];
    }
    if (tid < 16) { m_s[tid] = -1e30f; l_s[tid] = 0.0f; }

    float acc[8];
    #pragma unroll
    for (int j = 0; j < 8; j++) acc[j] = 0.0f;

    const int qg  = qt * 16 + r;
    const int nkt = ((qt * 16 + 15) >> 6) + 1;

    for (int kt = 0; kt < nkt; kt++) {
        __syncthreads();
        for (int i = tid; i < 64 * 16; i += 128) {
            int rr = i >> 4, c4 = (i & 15) << 2;
            int g  = ((b * TT + kt * 64 + rr) * CC) + h * DD + c4;
            *(float4*)&Ks[rr][c4] = *(const float4*)&K[g];
            *(float4*)&Vs[rr][c4] = *(const float4*)&V[g];
        }
        __syncthreads();

        float sv[8];
        #pragma unroll
        for (int j = 0; j < 8; j++) sv[j] = 0.0f;
        for (int d = 0; d < 64; d++) {
            float qv = Qs[r][d];
            #pragma unroll
            for (int j = 0; j < 8; j++) sv[j] += qv * Ks[sb + 8 * j][d];
        }
        float tmax = -1e30f;
        #pragma unroll
        for (int j = 0; j < 8; j++) {
            int sg = kt * 64 + sb + 8 * j;
            sv[j] = (sg <= qg) ? sv[j] * 0.125f : -1e30f;
            tmax = fmaxf(tmax, sv[j]);
        }
        #pragma unroll
        for (int o = 4; o; o >>= 1)
            tmax = fmaxf(tmax, __shfl_xor_sync(0xffffffffu, tmax, o, 8));

        float m_old = m_s[r];
        float m_new = fmaxf(m_old, tmax);
        float psum = 0.0f;
        #pragma unroll
        for (int j = 0; j < 8; j++) {
            float p = expf(sv[j] - m_new);
            Ps[r][sb + 8 * j] = p;
            psum += p;
        }
        #pragma unroll
        for (int o = 4; o; o >>= 1)
            psum += __shfl_xor_sync(0xffffffffu, psum, o, 8);

        float alpha = expf(m_old - m_new);
        if (sb == 0) { m_s[r] = m_new; l_s[r] = l_s[r] * alpha + psum; }
        __syncwarp();

        #pragma unroll
        for (int j = 0; j < 8; j++) acc[j] *= alpha;
        for (int s = 0; s < 64; s++) {
            float p = Ps[r][s];
            #pragma unroll
            for (int j = 0; j < 8; j++) acc[j] += p * Vs[s][sb + 8 * j];
        }
        __syncwarp();
    }

    float inv_l = 1.0f / l_s[r];
    #pragma unroll
    for (int j = 0; j < 8; j++)
        Y[((b * TT + qg) * CC) + h * DD + sb + 8 * j] = acc[j] * inv_l;
}

// ---------------------------------------------------------------------------
// Launch
// ---------------------------------------------------------------------------
extern "C" void kernel_launch(void* const* d_in, const int* in_sizes, int n_in,
                              void* d_out, int out_size)
{
    const int*   idx   = (const int*)  d_in[0];
    const float* tok   = (const float*)d_in[1];
    const float* pos   = (const float*)d_in[2];
    const float* ln1w  = (const float*)d_in[3];
    const float* ln1b  = (const float*)d_in[4];
    const float* Wq    = (const float*)d_in[5];
    const float* bq    = (const float*)d_in[6];
    const float* Wk    = (const float*)d_in[7];
    const float* bk    = (const float*)d_in[8];
    const float* Wv    = (const float*)d_in[9];
    const float* bv    = (const float*)d_in[10];
    const float* Wo    = (const float*)d_in[11];
    const float* bo    = (const float*)d_in[12];
    const float* ln2w  = (const float*)d_in[13];
    const float* ln2b  = (const float*)d_in[14];
    const float* W1    = (const float*)d_in[15];
    const float* b1    = (const float*)d_in[16];
    const float* W2    = (const float*)d_in[17];
    const float* b2    = (const float*)d_in[18];
    const float* lnfw  = (const float*)d_in[19];
    const float* lnfb  = (const float*)d_in[20];
    const float* Whead = (const float*)d_in[21];
    float* out = (float*)d_out;

    float *x, *h, *q, *k, *v, *y, *h1;
    cudaGetSymbolAddress((void**)&x,  g_x);
    cudaGetSymbolAddress((void**)&h,  g_h);
    cudaGetSymbolAddress((void**)&q,  g_q);
    cudaGetSymbolAddress((void**)&k,  g_k);
    cudaGetSymbolAddress((void**)&v,  g_v);
    cudaGetSymbolAddress((void**)&y,  g_y);
    cudaGetSymbolAddress((void**)&h1, g_h1);

    const int M = BB * TT;                   // 2048
    embed_kernel<<<(M * CC / 4 + 255) / 256, 256>>>(idx, tok, pos, x);

    for (int i = 0; i < LL; i++) {
        const int wOff  = i * CC * CC;
        const int bOff  = i * CC;
        const int w1Off = i * CC * 4 * CC;
        const int b1Off = i * 4 * CC;

        ln_kernel<<<M, 128>>>(x, ln1w + bOff, ln1b + bOff, h);

        gemm_tc<0><<<dim3(CC / 64, M / 128), 256>>>(h, Wq + wOff, bq + bOff, nullptr, q, M, CC, CC);
        gemm_tc<0><<<dim3(CC / 64, M / 128), 256>>>(h, Wk + wOff, bk + bOff, nullptr, k, M, CC, CC);
        gemm_tc<0><<<dim3(CC / 64, M / 128), 256>>>(h, Wv + wOff, bv + bOff, nullptr, v, M, CC, CC);

        attn_kernel<<<dim3(TT / 16, HH, BB), 128>>>(q, k, v, y);

        gemm_tc<1><<<dim3(CC / 64, M / 128), 256>>>(y, Wo + wOff, bo + bOff, x, x, M, CC, CC);

        ln_kernel<<<M, 128>>>(x, ln2w + bOff, ln2b + bOff, h);

        gemm_tc<2><<<dim3(4 * CC / 64, M / 128), 256>>>(h, W1 + w1Off, b1 + b1Off, nullptr, h1, M, 4 * CC, CC);
        gemm_tc<1><<<dim3(CC / 64, M / 128), 256>>>(h1, W2 + w1Off, b2 + bOff, x, x, M, CC, 4 * CC);
    }

    ln_kernel<<<M, 128>>>(x, lnfw, lnfb, h);
    gemm_tc<0><<<dim3(VV / 64, M / 128), 256>>>(h, Whead, nullptr, nullptr, out, M, VV, CC);
}

// round 6
// speedup vs baseline: 2.0476x; 1.1699x over previous
#include <cuda_runtime.h>
#include <cuda_bf16.h>
#include <math.h>
#include <stdint.h>

#define BB 2
#define TT 1024
#define CC 512
#define HH 8
#define DD 64
#define LL 4
#define VV 32000

typedef __nv_bfloat16 bf16;

// ---------------- scratch (no cudaMalloc allowed) ----------------
__device__ float g_x   [BB*TT*CC];          // residual stream (fp32)
__device__ float g_qkv [BB*TT*3*CC];        // fused qkv (fp32)
__device__ bf16  g_h_hi[BB*TT*CC],  g_h_lo[BB*TT*CC];     // LN out split
__device__ bf16  g_y_hi[BB*TT*CC],  g_y_lo[BB*TT*CC];     // attn out split
__device__ bf16  g_h1_hi[BB*TT*4*CC], g_h1_lo[BB*TT*4*CC];// MLP hidden split
// packed weights (transposed to [N][K], split hi/lo)
__device__ bf16 g_wqkv_hi[LL*3*CC*CC], g_wqkv_lo[LL*3*CC*CC];
__device__ bf16 g_wo_hi  [LL*CC*CC],   g_wo_lo  [LL*CC*CC];
__device__ bf16 g_w1_hi  [LL*4*CC*CC], g_w1_lo  [LL*4*CC*CC];
__device__ bf16 g_w2_hi  [LL*4*CC*CC], g_w2_lo  [LL*4*CC*CC];
__device__ bf16 g_wh_hi  [VV*CC],      g_wh_lo  [VV*CC];
__device__ float g_bqkv [LL*3*CC];

// ---------------------------------------------------------------------------
// Weight pack: out_hi/lo[n][k] = split(W[k][n]).  32x32 tiled transpose.
// ---------------------------------------------------------------------------
__global__ __launch_bounds__(256) void pack_w(const float* __restrict__ W,
                                              bf16* __restrict__ hi,
                                              bf16* __restrict__ lo,
                                              int K, int N)
{
    __shared__ float t[32][33];
    const int n0 = blockIdx.x * 32, k0 = blockIdx.y * 32;
    const int tx = threadIdx.x, ty = threadIdx.y;   // 32 x 8
    #pragma unroll
    for (int i = 0; i < 4; i++)
        t[ty + i * 8][tx] = W[(size_t)(k0 + ty + i * 8) * N + n0 + tx];
    __syncthreads();
    #pragma unroll
    for (int i = 0; i < 4; i++) {
        int n = n0 + ty + i * 8;
        float v = t[tx][ty + i * 8];
        bf16 h = __float2bfloat16(v);
        hi[(size_t)n * K + k0 + tx] = h;
        lo[(size_t)n * K + k0 + tx] = __float2bfloat16(v - __bfloat162float(h));
    }
}

__global__ void pack_bqkv(const float* __restrict__ bq, const float* __restrict__ bk,
                          const float* __restrict__ bv, float* __restrict__ out)
{
    int i = blockIdx.x * 256 + threadIdx.x;
    if (i >= LL * 3 * CC) return;
    int l = i / (3 * CC), c = i % (3 * CC);
    float v = (c < CC) ? bq[l * CC + c]
            : (c < 2 * CC) ? bk[l * CC + c - CC] : bv[l * CC + c - 2 * CC];
    out[i] = v;
}

// ---------------------------------------------------------------------------
// Embedding
// ---------------------------------------------------------------------------
__global__ void embed_kernel(const int* __restrict__ idx,
                             const float* __restrict__ tok,
                             const float* __restrict__ pos,
                             float* __restrict__ x)
{
    int i  = blockIdx.x * blockDim.x + threadIdx.x;
    int c4 = (i & 127) << 2;
    int bt = i >> 7;
    int t  = bt & (TT - 1);
    int row = idx[bt];
    float4 a = *(const float4*)&tok[row * CC + c4];
    float4 p = *(const float4*)&pos[t   * CC + c4];
    float4 o;
    o.x = a.x + p.x; o.y = a.y + p.y; o.z = a.z + p.z; o.w = a.w + p.w;
    *(float4*)&x[bt * CC + c4] = o;
}

// ---------------------------------------------------------------------------
// LayerNorm -> split bf16 hi/lo outputs
// ---------------------------------------------------------------------------
__global__ __launch_bounds__(128) void ln_split(const float* __restrict__ x,
                                                const float* __restrict__ w,
                                                const float* __restrict__ b,
                                                bf16* __restrict__ ohi,
                                                bf16* __restrict__ olo)
{
    __shared__ float red[4];
    const int row = blockIdx.x;
    const int tid = threadIdx.x;

    float4 v = *(const float4*)&x[row * CC + tid * 4];
    float s = v.x + v.y + v.z + v.w;
    #pragma unroll
    for (int o = 16; o; o >>= 1) s += __shfl_xor_sync(0xffffffffu, s, o);
    if ((tid & 31) == 0) red[tid >> 5] = s;
    __syncthreads();
    float mean = (red[0] + red[1] + red[2] + red[3]) * (1.0f / CC);

    float d0 = v.x - mean, d1 = v.y - mean, d2 = v.z - mean, d3 = v.w - mean;
    float ss = d0*d0 + d1*d1 + d2*d2 + d3*d3;
    #pragma unroll
    for (int o = 16; o; o >>= 1) ss += __shfl_xor_sync(0xffffffffu, ss, o);
    __syncthreads();
    if ((tid & 31) == 0) red[tid >> 5] = ss;
    __syncthreads();
    float var  = (red[0] + red[1] + red[2] + red[3]) * (1.0f / CC);
    float rstd = rsqrtf(var + 1e-5f);

    float4 wv = *(const float4*)&w[tid * 4];
    float4 bv = *(const float4*)&b[tid * 4];
    float o4[4];
    o4[0] = d0 * rstd * wv.x + bv.x;
    o4[1] = d1 * rstd * wv.y + bv.y;
    o4[2] = d2 * rstd * wv.z + bv.z;
    o4[3] = d3 * rstd * wv.w + bv.w;

    bf16 hi[4], lo[4];
    #pragma unroll
    for (int j = 0; j < 4; j++) {
        hi[j] = __float2bfloat16(o4[j]);
        lo[j] = __float2bfloat16(o4[j] - __bfloat162float(hi[j]));
    }
    *(uint2*)&ohi[row * CC + tid * 4] = *(uint2*)hi;
    *(uint2*)&olo[row * CC + tid * 4] = *(uint2*)lo;
}

// ---------------------------------------------------------------------------
// Tensor-core GEMM, pre-split bf16 operands (hi*hi+hi*lo+lo*hi, fp32 accum).
// A: [M][K] bf16 hi/lo, B: [N][K] bf16 hi/lo (transposed at pack time).
// Tile BM x 64 x 32, warps WM x 2, warp tile 32x32, cp.async 2-stage.
// MODE: 0 = bias->fp32, 1 = bias+resid->fp32, 2 = gelu(bias)->split bf16
// ---------------------------------------------------------------------------
#define SWZ(r) ((((r) >> 1) & 3) << 2)

__device__ __forceinline__ void mma_bf16(float* c, const uint32_t* a, const uint32_t* b)
{
    asm volatile(
        "mma.sync.aligned.m16n8k16.row.col.f32.bf16.bf16.f32 "
        "{%0,%1,%2,%3}, {%4,%5,%6,%7}, {%8,%9}, {%0,%1,%2,%3};"
        : "+f"(c[0]), "+f"(c[1]), "+f"(c[2]), "+f"(c[3])
        : "r"(a[0]), "r"(a[1]), "r"(a[2]), "r"(a[3]), "r"(b[0]), "r"(b[1]));
}

__device__ __forceinline__ void cp16(uint32_t dst, const void* src)
{
    asm volatile("cp.async.cg.shared.global [%0], [%1], 16;\n"
                 :: "r"(dst), "l"(src));
}

template<int MODE, int WM>
__global__ __launch_bounds__(WM * 64) void gemm_tc2(
    const bf16* __restrict__ Ah, const bf16* __restrict__ Al,
    const bf16* __restrict__ Bh, const bf16* __restrict__ Bl,
    const float* __restrict__ bias, const float* __restrict__ resid,
    float* __restrict__ C, bf16* __restrict__ Chi, bf16* __restrict__ Clo,
    int M, int N, int K)
{
    constexpr int BM  = WM * 32;
    constexpr int NT  = WM * 64;
    constexpr int LA  = (WM == 4) ? 9 : 8;    // log2(BM*4) A-chunks per hl
    constexpr int BPT = 512 / NT;             // B chunks per thread

    __shared__ __align__(16) uint32_t As[2][2][BM][16];
    __shared__ __align__(16) uint32_t Bs[2][2][64][16];

    const int tid = threadIdx.x;
    const int lid = tid & 31;
    const int wid = tid >> 5;
    const int warp_m = wid % WM;
    const int warp_n = wid / WM;
    const int bm = blockIdx.y * BM;
    const int bn = blockIdx.x * 64;

    float acc[2][4][4];
    #pragma unroll
    for (int i = 0; i < 2; i++)
        #pragma unroll
        for (int j = 0; j < 4; j++)
            #pragma unroll
            for (int q = 0; q < 4; q++) acc[i][j][q] = 0.0f;

    // stage loader: A = BM*8 16B-chunks, B = 512 16B-chunks
    auto load_stage = [&](int st, int k0) {
        #pragma unroll
        for (int i = 0; i < 4; i++) {
            int id  = tid + i * NT;
            int c   = id & 3;
            int row = (id >> 2) & (BM - 1);
            int hl  = id >> LA;
            const bf16* src = (hl ? Al : Ah) + (size_t)(bm + row) * K + k0 + c * 8;
            uint32_t dst = (uint32_t)__cvta_generic_to_shared(
                &As[st][hl][row][(c ^ ((row >> 1) & 3)) << 2]);
            cp16(dst, src);
        }
        #pragma unroll
        for (int i = 0; i < BPT; i++) {
            int id = tid + i * NT;
            int c  = id & 3;
            int n  = (id >> 2) & 63;
            int hl = id >> 8;
            const bf16* src = (hl ? Bl : Bh) + (size_t)(bn + n) * K + k0 + c * 8;
            uint32_t dst = (uint32_t)__cvta_generic_to_shared(
                &Bs[st][hl][n][(c ^ ((n >> 1) & 3)) << 2]);
            cp16(dst, src);
        }
    };

    const int nst = K / 32;
    load_stage(0, 0);
    asm volatile("cp.async.commit_group;" ::: "memory");
    load_stage(1, 32);
    asm volatile("cp.async.commit_group;" ::: "memory");

    int buf = 0;
    for (int st = 0; st < nst; st++) {
        if (st == nst - 1) asm volatile("cp.async.wait_group 0;" ::: "memory");
        else               asm volatile("cp.async.wait_group 1;" ::: "memory");
        __syncthreads();

        #pragma unroll
        for (int s = 0; s <= 8; s += 8) {
            const int c = lid & 3;
            uint32_t Af[2][2][4];
            uint32_t Bf[2][4][2];
            #pragma unroll
            for (int mt = 0; mt < 2; mt++) {
                int m0 = warp_m * 32 + mt * 16 + (lid >> 2);
                int m1 = m0 + 8;
                int p0 = (s + c)     ^ SWZ(m0);
                int p1 = (s + c)     ^ SWZ(m1);
                int p2 = (s + 4 + c) ^ SWZ(m0);
                int p3 = (s + 4 + c) ^ SWZ(m1);
                #pragma unroll
                for (int hl = 0; hl < 2; hl++) {
                    Af[hl][mt][0] = As[buf][hl][m0][p0];
                    Af[hl][mt][1] = As[buf][hl][m1][p1];
                    Af[hl][mt][2] = As[buf][hl][m0][p2];
                    Af[hl][mt][3] = As[buf][hl][m1][p3];
                }
            }
            #pragma unroll
            for (int nt = 0; nt < 4; nt++) {
                int n0 = warp_n * 32 + nt * 8 + (lid >> 2);
                int p0 = (s + c)     ^ SWZ(n0);
                int p1 = (s + 4 + c) ^ SWZ(n0);
                #pragma unroll
                for (int hl = 0; hl < 2; hl++) {
                    Bf[hl][nt][0] = Bs[buf][hl][n0][p0];
                    Bf[hl][nt][1] = Bs[buf][hl][n0][p1];
                }
            }
            #pragma unroll
            for (int mt = 0; mt < 2; mt++)
                #pragma unroll
                for (int nt = 0; nt < 4; nt++) {
                    mma_bf16(acc[mt][nt], Af[0][mt], Bf[0][nt]);   // hi*hi
                    mma_bf16(acc[mt][nt], Af[0][mt], Bf[1][nt]);   // hi*lo
                    mma_bf16(acc[mt][nt], Af[1][mt], Bf[0][nt]);   // lo*hi
                }
        }

        if (st + 2 < nst) {
            __syncthreads();
            load_stage(buf, (st + 2) * 32);
            asm volatile("cp.async.commit_group;" ::: "memory");
        }
        buf ^= 1;
    }

    // epilogue
    #pragma unroll
    for (int mt = 0; mt < 2; mt++) {
        #pragma unroll
        for (int nt = 0; nt < 4; nt++) {
            int r0 = bm + warp_m * 32 + mt * 16 + (lid >> 2);
            int cc = bn + warp_n * 32 + nt * 8 + ((lid & 3) << 1);
            float2 bb = make_float2(0.0f, 0.0f);
            if (bias) bb = *(const float2*)(bias + cc);
            float* a4 = acc[mt][nt];
            #pragma unroll
            for (int half = 0; half < 2; half++) {
                int row = r0 + half * 8;
                float o0 = a4[half * 2 + 0] + bb.x;
                float o1 = a4[half * 2 + 1] + bb.y;
                if (MODE == 1) {
                    float2 rr = *(const float2*)(resid + (size_t)row * N + cc);
                    o0 += rr.x; o1 += rr.y;
                }
                if (MODE == 2) {
                    o0 = 0.5f * o0 * (1.0f + erff(o0 * 0.70710678118654752f));
                    o1 = 0.5f * o1 * (1.0f + erff(o1 * 0.70710678118654752f));
                    __nv_bfloat162 h2, l2;
                    h2.x = __float2bfloat16(o0);
                    h2.y = __float2bfloat16(o1);
                    l2.x = __float2bfloat16(o0 - __bfloat162float(h2.x));
                    l2.y = __float2bfloat16(o1 - __bfloat162float(h2.y));
                    *(__nv_bfloat162*)(Chi + (size_t)row * N + cc) = h2;
                    *(__nv_bfloat162*)(Clo + (size_t)row * N + cc) = l2;
                } else {
                    *(float2*)(C + (size_t)row * N + cc) = make_float2(o0, o1);
                }
            }
        }
    }
}

// ---------------------------------------------------------------------------
// Flash attention (fp32, causal) reading fused qkv [M][1536]; split output.
// ---------------------------------------------------------------------------
__global__ __launch_bounds__(128) void attn_kernel(
    const float* __restrict__ QKV, bf16* __restrict__ Yh, bf16* __restrict__ Yl)
{
    const int qt = blockIdx.x;
    const int h  = blockIdx.y;
    const int b  = blockIdx.z;

    __shared__ float Qs[16][68];
    __shared__ float Ks[64][68];
    __shared__ float Vs[64][68];
    __shared__ float Ps[16][65];
    __shared__ float m_s[16], l_s[16];

    const int tid = threadIdx.x;
    const int r  = tid >> 3;
    const int sb = tid & 7;
    const int qofs = h * DD;
    const int kofs = CC + h * DD;
    const int vofs = 2 * CC + h * DD;
    const int ST = 3 * CC;

    for (int i = tid; i < 16 * 16; i += 128) {
        int rr = i >> 4, c4 = (i & 15) << 2;
        *(float4*)&Qs[rr][c4] =
            *(const float4*)&QKV[((size_t)(b * TT + qt * 16 + rr)) * ST + qofs + c4];
    }
    if (tid < 16) { m_s[tid] = -1e30f; l_s[tid] = 0.0f; }

    float acc[8];
    #pragma unroll
    for (int j = 0; j < 8; j++) acc[j] = 0.0f;

    const int qg  = qt * 16 + r;
    const int nkt = ((qt * 16 + 15) >> 6) + 1;

    for (int kt = 0; kt < nkt; kt++) {
        __syncthreads();
        for (int i = tid; i < 64 * 16; i += 128) {
            int rr = i >> 4, c4 = (i & 15) << 2;
            size_t g = ((size_t)(b * TT + kt * 64 + rr)) * ST;
            *(float4*)&Ks[rr][c4] = *(const float4*)&QKV[g + kofs + c4];
            *(float4*)&Vs[rr][c4] = *(const float4*)&QKV[g + vofs + c4];
        }
        __syncthreads();

        float sv[8];
        #pragma unroll
        for (int j = 0; j < 8; j++) sv[j] = 0.0f;
        for (int d = 0; d < 64; d++) {
            float qv = Qs[r][d];
            #pragma unroll
            for (int j = 0; j < 8; j++) sv[j] += qv * Ks[sb + 8 * j][d];
        }
        float tmax = -1e30f;
        #pragma unroll
        for (int j = 0; j < 8; j++) {
            int sg = kt * 64 + sb + 8 * j;
            sv[j] = (sg <= qg) ? sv[j] * 0.125f : -1e30f;
            tmax = fmaxf(tmax, sv[j]);
        }
        #pragma unroll
        for (int o = 4; o; o >>= 1)
            tmax = fmaxf(tmax, __shfl_xor_sync(0xffffffffu, tmax, o, 8));

        float m_old = m_s[r];
        float m_new = fmaxf(m_old, tmax);
        float psum = 0.0f;
        #pragma unroll
        for (int j = 0; j < 8; j++) {
            float p = expf(sv[j] - m_new);
            Ps[r][sb + 8 * j] = p;
            psum += p;
        }
        #pragma unroll
        for (int o = 4; o; o >>= 1)
            psum += __shfl_xor_sync(0xffffffffu, psum, o, 8);

        float alpha = expf(m_old - m_new);
        if (sb == 0) { m_s[r] = m_new; l_s[r] = l_s[r] * alpha + psum; }
        __syncwarp();

        #pragma unroll
        for (int j = 0; j < 8; j++) acc[j] *= alpha;
        for (int s = 0; s < 64; s++) {
            float p = Ps[r][s];
            #pragma unroll
            for (int j = 0; j < 8; j++) acc[j] += p * Vs[s][sb + 8 * j];
        }
        __syncwarp();
    }

    float inv_l = 1.0f / l_s[r];
    #pragma unroll
    for (int j = 0; j < 8; j++) {
        float v = acc[j] * inv_l;
        bf16 hv = __float2bfloat16(v);
        size_t o = ((size_t)(b * TT + qg)) * CC + h * DD + sb + 8 * j;
        Yh[o] = hv;
        Yl[o] = __float2bfloat16(v - __bfloat162float(hv));
    }
}

// ---------------------------------------------------------------------------
// Launch
// ---------------------------------------------------------------------------
extern "C" void kernel_launch(void* const* d_in, const int* in_sizes, int n_in,
                              void* d_out, int out_size)
{
    const int*   idx   = (const int*)  d_in[0];
    const float* tok   = (const float*)d_in[1];
    const float* pos   = (const float*)d_in[2];
    const float* ln1w  = (const float*)d_in[3];
    const float* ln1b  = (const float*)d_in[4];
    const float* Wq    = (const float*)d_in[5];
    const float* bq    = (const float*)d_in[6];
    const float* Wk    = (const float*)d_in[7];
    const float* bk    = (const float*)d_in[8];
    const float* Wv    = (const float*)d_in[9];
    const float* bv    = (const float*)d_in[10];
    const float* Wo    = (const float*)d_in[11];
    const float* bo    = (const float*)d_in[12];
    const float* ln2w  = (const float*)d_in[13];
    const float* ln2b  = (const float*)d_in[14];
    const float* W1    = (const float*)d_in[15];
    const float* b1    = (const float*)d_in[16];
    const float* W2    = (const float*)d_in[17];
    const float* b2    = (const float*)d_in[18];
    const float* lnfw  = (const float*)d_in[19];
    const float* lnfb  = (const float*)d_in[20];
    const float* Whead = (const float*)d_in[21];
    float* out = (float*)d_out;

    float *x, *qkv, *bqkv;
    bf16 *h_hi, *h_lo, *y_hi, *y_lo, *h1_hi, *h1_lo;
    bf16 *wqkv_hi, *wqkv_lo, *wo_hi, *wo_lo, *w1_hi, *w1_lo, *w2_hi, *w2_lo, *wh_hi, *wh_lo;
    cudaGetSymbolAddress((void**)&x,     g_x);
    cudaGetSymbolAddress((void**)&qkv,   g_qkv);
    cudaGetSymbolAddress((void**)&bqkv,  g_bqkv);
    cudaGetSymbolAddress((void**)&h_hi,  g_h_hi);
    cudaGetSymbolAddress((void**)&h_lo,  g_h_lo);
    cudaGetSymbolAddress((void**)&y_hi,  g_y_hi);
    cudaGetSymbolAddress((void**)&y_lo,  g_y_lo);
    cudaGetSymbolAddress((void**)&h1_hi, g_h1_hi);
    cudaGetSymbolAddress((void**)&h1_lo, g_h1_lo);
    cudaGetSymbolAddress((void**)&wqkv_hi, g_wqkv_hi);
    cudaGetSymbolAddress((void**)&wqkv_lo, g_wqkv_lo);
    cudaGetSymbolAddress((void**)&wo_hi,   g_wo_hi);
    cudaGetSymbolAddress((void**)&wo_lo,   g_wo_lo);
    cudaGetSymbolAddress((void**)&w1_hi,   g_w1_hi);
    cudaGetSymbolAddress((void**)&w1_lo,   g_w1_lo);
    cudaGetSymbolAddress((void**)&w2_hi,   g_w2_hi);
    cudaGetSymbolAddress((void**)&w2_lo,   g_w2_lo);
    cudaGetSymbolAddress((void**)&wh_hi,   g_wh_hi);
    cudaGetSymbolAddress((void**)&wh_lo,   g_wh_lo);

    const int M = BB * TT;
    const dim3 tb(32, 8);

    // ---- prepack weights (transpose + bf16 split) ----
    for (int l = 0; l < LL; l++) {
        const size_t w  = (size_t)l * CC * CC;
        const size_t w1 = (size_t)l * 4 * CC * CC;
        pack_w<<<dim3(16, 16), tb>>>(Wq + w, wqkv_hi + (size_t)l*3*CC*CC,
                                     wqkv_lo + (size_t)l*3*CC*CC, CC, CC);
        pack_w<<<dim3(16, 16), tb>>>(Wk + w, wqkv_hi + (size_t)l*3*CC*CC + CC*CC,
                                     wqkv_lo + (size_t)l*3*CC*CC + CC*CC, CC, CC);
        pack_w<<<dim3(16, 16), tb>>>(Wv + w, wqkv_hi + (size_t)l*3*CC*CC + 2*CC*CC,
                                     wqkv_lo + (size_t)l*3*CC*CC + 2*CC*CC, CC, CC);
        pack_w<<<dim3(16, 16), tb>>>(Wo + w, wo_hi + w, wo_lo + w, CC, CC);
        pack_w<<<dim3(64, 16), tb>>>(W1 + w1, w1_hi + w1, w1_lo + w1, CC, 4 * CC);
        pack_w<<<dim3(16, 64), tb>>>(W2 + w1, w2_hi + w1, w2_lo + w1, 4 * CC, CC);
    }
    pack_w<<<dim3(VV / 32, 16), tb>>>(Whead, wh_hi, wh_lo, CC, VV);
    pack_bqkv<<<(LL * 3 * CC + 255) / 256, 256>>>(bq, bk, bv, bqkv);

    embed_kernel<<<(M * CC / 4 + 255) / 256, 256>>>(idx, tok, pos, x);

    for (int l = 0; l < LL; l++) {
        const size_t bOff  = (size_t)l * CC;
        const size_t b1Off = (size_t)l * 4 * CC;

        ln_split<<<M, 128>>>(x, ln1w + bOff, ln1b + bOff, h_hi, h_lo);

        gemm_tc2<0, 4><<<dim3(24, 16), 256>>>(
            h_hi, h_lo, wqkv_hi + (size_t)l*3*CC*CC, wqkv_lo + (size_t)l*3*CC*CC,
            bqkv + (size_t)l*3*CC, nullptr, qkv, nullptr, nullptr, M, 3 * CC, CC);

        attn_kernel<<<dim3(TT / 16, HH, BB), 128>>>(qkv, y_hi, y_lo);

        gemm_tc2<1, 2><<<dim3(8, 32), 128>>>(
            y_hi, y_lo, wo_hi + (size_t)l*CC*CC, wo_lo + (size_t)l*CC*CC,
            bo + bOff, x, x, nullptr, nullptr, M, CC, CC);

        ln_split<<<M, 128>>>(x, ln2w + bOff, ln2b + bOff, h_hi, h_lo);

        gemm_tc2<2, 4><<<dim3(32, 16), 256>>>(
            h_hi, h_lo, w1_hi + (size_t)l*4*CC*CC, w1_lo + (size_t)l*4*CC*CC,
            b1 + b1Off, nullptr, nullptr, h1_hi, h1_lo, M, 4 * CC, CC);

        gemm_tc2<1, 2><<<dim3(8, 32), 128>>>(
            h1_hi, h1_lo, w2_hi + (size_t)l*4*CC*CC, w2_lo + (size_t)l*4*CC*CC,
            b2 + bOff, x, x, nullptr, nullptr, M, CC, 4 * CC);
    }

    ln_split<<<M, 128>>>(x, lnfw, lnfb, h_hi, h_lo);
    gemm_tc2<0, 4><<<dim3(VV / 64, 16), 256>>>(
        h_hi, h_lo, wh_hi, wh_lo, nullptr, nullptr, out, nullptr, nullptr, M, VV, CC);
}